// round 4
// baseline (speedup 1.0000x reference)
#include <cuda_runtime.h>

#define BB 65536
#define VV 4
#define BPB 32
#define THREADS 128
#define NBLK (BB / BPB)              // 2048

// shared layout (float offsets)
#define KW_OFF   0                   // 32 batches x stride 100 (24 f4 data + pad)
#define CAM_OFF  3200                // 32 x stride 49 (48 data + 1 pad, odd stride)
#define KK_OFF   4768                // 32 x stride 37 (36 data + 1 pad, odd stride)
#define IK_OFF   5952                // ik transposed: 16 rows x 129 f4 (stride 516 floats)
#define IK_F4    (IK_OFF / 4)        // 1488
#define IK_S4    129
#define SMEM_FLOATS (IK_OFF + 16 * 516)   // 14208
#define SMEM_BYTES  (SMEM_FLOATS * 4)     // 56832 -> 4 blocks/SM

__device__ float g_partials[NBLK];
__device__ unsigned int g_ticket;

static __device__ __forceinline__ float warp_sum(float v) {
#pragma unroll
    for (int o = 16; o; o >>= 1) v += __shfl_xor_sync(0xFFFFFFFFu, v, o);
    return v;
}

__global__ __launch_bounds__(THREADS, 4) void proj_loss(
    const float* __restrict__ Kmat,   // (B,V,3,3)
    const float* __restrict__ cam,    // (B,V,3,4)
    const float* __restrict__ kw,     // (B,J,3)
    const float* __restrict__ ik,     // (B,V,J,2)
    float* __restrict__ out)
{
    extern __shared__ float sm[];
    float4* sm4 = (float4*)sm;
    __shared__ float s_w[4];
    __shared__ int s_last;

    const int tid = threadIdx.x;
    const int b0 = blockIdx.x * BPB;

    // ------------------- staging: all gmem loads coalesced f4 -------------------
    {   // kw: 768 f4 -> rows stride 25 f4
        const float4* g = (const float4*)(kw + (size_t)b0 * 96);
#pragma unroll
        for (int r = 0; r < 6; ++r) {
            int i = tid + r * 128, b = i / 24, k = i - b * 24;
            sm4[b * 25 + k] = __ldcs(&g[i]);
        }
    }
    {   // cam: 384 f4 -> scalar scatter to odd-stride rows
        const float4* g = (const float4*)(cam + (size_t)b0 * 48);
#pragma unroll
        for (int r = 0; r < 3; ++r) {
            int i = tid + r * 128, b = i / 12, k = i - b * 12;
            float4 val = __ldcs(&g[i]);
            int base = CAM_OFF + b * 49 + k * 4;
            sm[base] = val.x; sm[base + 1] = val.y;
            sm[base + 2] = val.z; sm[base + 3] = val.w;
        }
    }
    {   // K: 288 f4
        const float4* g = (const float4*)(Kmat + (size_t)b0 * 36);
#pragma unroll
        for (int r = 0; r < 3; ++r) {
            int i = tid + r * 128;
            if (i < 288) {
                int b = i / 9, k = i - b * 9;
                float4 val = __ldcs(&g[i]);
                int base = KK_OFF + b * 37 + k * 4;
                sm[base] = val.x; sm[base + 1] = val.y;
                sm[base + 2] = val.z; sm[base + 3] = val.w;
            }
        }
    }
    {   // ik: 2048 f4 -> TRANSPOSED [f4-slot g][task t], conflict-free reads later
        const float4* g = (const float4*)(ik + (size_t)b0 * 256);
#pragma unroll
        for (int r = 0; r < 16; ++r) {
            int i = tid + r * 128;
            int t = i >> 4, gg = i & 15;
            sm4[IK_F4 + gg * IK_S4 + t] = __ldcs(&g[i]);
        }
    }
    __syncthreads();

    // ------------------- one thread per (batch, view) task -------------------
    const int bl = tid >> 2, v = tid & 3;
    const float* cv = &sm[CAM_OFF + bl * 49 + v * 12];
    const float R00=cv[0], R01=cv[1], R02=cv[2],  t0=cv[3];
    const float R10=cv[4], R11=cv[5], R12=cv[6],  t1=cv[7];
    const float R20=cv[8], R21=cv[9], R22=cv[10], t2=cv[11];
    const float* kp = &sm[KK_OFF + bl * 37 + v * 9];
    const float K00=kp[0], K01=kp[1], c0=kp[2];
    const float K10=kp[3], K11=kp[4], c1=kp[5];

    const int xb = bl * 25;           // f4 base of this batch's X row

    // pass A (view-cooperative): each of 4 view-lanes sums 1/4 of the joints
    float Sx = 0.f, Sy = 0.f, Sz = 0.f;
#pragma unroll
    for (int q = 0; q < 2; ++q) {
        float4 p0 = sm4[xb + v * 6 + q * 3];
        float4 p1 = sm4[xb + v * 6 + q * 3 + 1];
        float4 p2 = sm4[xb + v * 6 + q * 3 + 2];
        Sx += p0.x + p0.w + p1.z + p2.y;
        Sy += p0.y + p1.x + p1.w + p2.z;
        Sz += p0.z + p1.y + p2.x + p2.w;
    }
    Sx += __shfl_xor_sync(0xFFFFFFFFu, Sx, 1); Sx += __shfl_xor_sync(0xFFFFFFFFu, Sx, 2);
    Sy += __shfl_xor_sync(0xFFFFFFFFu, Sy, 1); Sy += __shfl_xor_sync(0xFFFFFFFFu, Sy, 2);
    Sz += __shfl_xor_sync(0xFFFFFFFFu, Sz, 1); Sz += __shfl_xor_sync(0xFFFFFFFFu, Sz, 2);

    const float zbar = fmaf(R20, Sx, fmaf(R21, Sy, R22 * Sz)) * (1.0f / 32.0f) + t2;
    const float izb  = __fdividef(1.0f, zbar);

    // fold K * R * inv_z: uv = a . X + b
    const float a0x = izb * fmaf(K00, R00, K01 * R10);
    const float a0y = izb * fmaf(K00, R01, K01 * R11);
    const float a0z = izb * fmaf(K00, R02, K01 * R12);
    const float b0u = fmaf(izb, fmaf(K00, t0, K01 * t1), c0);
    const float a1x = izb * fmaf(K10, R00, K11 * R10);
    const float a1y = izb * fmaf(K10, R01, K11 * R11);
    const float a1z = izb * fmaf(K10, R02, K11 * R12);
    const float b1u = fmaf(izb, fmaf(K10, t0, K11 * t1), c1);

    // pass B: squared norms (uv recomputed later; no big register array)
    float np2 = 0.f, ni2 = 0.f;
#pragma unroll
    for (int g = 0; g < 8; ++g) {
        float4 p0 = sm4[xb + g * 3];
        float4 p1 = sm4[xb + g * 3 + 1];
        float4 p2 = sm4[xb + g * 3 + 2];
        float xs[4] = {p0.x, p0.w, p1.z, p2.y};
        float ys[4] = {p0.y, p1.x, p1.w, p2.z};
        float zs[4] = {p0.z, p1.y, p2.x, p2.w};
#pragma unroll
        for (int q = 0; q < 4; ++q) {
            float ux = fmaf(a0x, xs[q], fmaf(a0y, ys[q], fmaf(a0z, zs[q], b0u)));
            float uy = fmaf(a1x, xs[q], fmaf(a1y, ys[q], fmaf(a1z, zs[q], b1u)));
            np2 = fmaf(ux, ux, fmaf(uy, uy, np2));
        }
        float4 q0 = sm4[IK_F4 + (2 * g)     * IK_S4 + tid];
        float4 q1 = sm4[IK_F4 + (2 * g + 1) * IK_S4 + tid];
        ni2 = fmaf(q0.x, q0.x, fmaf(q0.y, q0.y, ni2));
        ni2 = fmaf(q0.z, q0.z, fmaf(q0.w, q0.w, ni2));
        ni2 = fmaf(q1.x, q1.x, fmaf(q1.y, q1.y, ni2));
        ni2 = fmaf(q1.z, q1.z, fmaf(q1.w, q1.w, ni2));
    }
    const float rp = rsqrtf(np2);
    const float ri = rsqrtf(ni2);

    // pass C: recompute uv, accumulate L1 of scale-free difference
    float acc = 0.f;
#pragma unroll
    for (int g = 0; g < 8; ++g) {
        float4 p0 = sm4[xb + g * 3];
        float4 p1 = sm4[xb + g * 3 + 1];
        float4 p2 = sm4[xb + g * 3 + 2];
        float xs[4] = {p0.x, p0.w, p1.z, p2.y};
        float ys[4] = {p0.y, p1.x, p1.w, p2.z};
        float zs[4] = {p0.z, p1.y, p2.x, p2.w};
        float4 q0 = sm4[IK_F4 + (2 * g)     * IK_S4 + tid];
        float4 q1 = sm4[IK_F4 + (2 * g + 1) * IK_S4 + tid];
        float qx[4] = {q0.x, q0.z, q1.x, q1.z};
        float qy[4] = {q0.y, q0.w, q1.y, q1.w};
#pragma unroll
        for (int q = 0; q < 4; ++q) {
            float ux = fmaf(a0x, xs[q], fmaf(a0y, ys[q], fmaf(a0z, zs[q], b0u)));
            float uy = fmaf(a1x, xs[q], fmaf(a1y, ys[q], fmaf(a1z, zs[q], b1u)));
            acc += fabsf(fmaf(ux, rp, -qx[q] * ri))
                 + fabsf(fmaf(uy, rp, -qy[q] * ri));
        }
    }

    // ------------------- block partial + last-block deterministic reduce -----
    acc = warp_sum(acc);
    if ((tid & 31) == 0) s_w[tid >> 5] = acc;
    __syncthreads();
    if (tid == 0) {
        float bsum = s_w[0] + s_w[1] + s_w[2] + s_w[3];
        __stcg(&g_partials[blockIdx.x], bsum);
        __threadfence();
        unsigned int t = atomicAdd(&g_ticket, 1u);
        s_last = (t == NBLK - 1u);
    }
    __syncthreads();

    if (s_last) {
        float a = 0.f;
#pragma unroll
        for (int i = 0; i < NBLK / THREADS; ++i)
            a += __ldcg(&g_partials[tid * (NBLK / THREADS) + i]);
        a = warp_sum(a);
        if ((tid & 31) == 0) s_w[tid >> 5] = a;
        __syncthreads();
        if (tid == 0) {
            float tot = s_w[0] + s_w[1] + s_w[2] + s_w[3];
            out[0] = tot * (1.0f / (64.0f * (float)BB * (float)VV));
            g_ticket = 0u;
        }
    }
}

extern "C" void kernel_launch(void* const* d_in, const int* in_sizes, int n_in,
                              void* d_out, int out_size)
{
    const float* Kmat = (const float*)d_in[0];  // (B,V,3,3)
    const float* cam  = (const float*)d_in[1];  // (B,V,3,4)
    const float* kw   = (const float*)d_in[2];  // (B,J,3)
    const float* ik   = (const float*)d_in[3];  // (B,V,J,2)
    float* out = (float*)d_out;

    cudaFuncSetAttribute(proj_loss, cudaFuncAttributeMaxDynamicSharedMemorySize, SMEM_BYTES);
    proj_loss<<<NBLK, THREADS, SMEM_BYTES>>>(Kmat, cam, kw, ik, out);
}

// round 5
// speedup vs baseline: 1.2396x; 1.2396x over previous
#include <cuda_runtime.h>

#define BB 65536
#define VV 4
#define BPB 16                        // batches per block
#define THREADS 128                   // 2 threads per (batch,view) task
#define NBLK (BB / BPB)               // 4096

// shared layout, f4 units unless noted
#define KW4   0                       // 16 batches x stride 25 f4 (24 data + 1 pad)
#define IK4   400                     // transposed: 8 slots x stride 129 f4
#define CAMF  5728                    // floats: 16 x stride 49 (48 data + 1 pad)
#define KKF   6512                    // floats: 16 x stride 37 (36 data + 1 pad)
#define SMEM_FLOATS 7104
#define SMEM_BYTES (SMEM_FLOATS * 4)  // 28416

__device__ float g_partials[NBLK];
__device__ unsigned int g_ticket;

static __device__ __forceinline__ float warp_sum(float v) {
#pragma unroll
    for (int o = 16; o; o >>= 1) v += __shfl_xor_sync(0xFFFFFFFFu, v, o);
    return v;
}

__global__ __launch_bounds__(THREADS, 5) void proj_loss(
    const float* __restrict__ Kmat,   // (B,V,3,3)
    const float* __restrict__ cam,    // (B,V,3,4)
    const float* __restrict__ kw,     // (B,J,3)
    const float* __restrict__ ik,     // (B,V,J,2)
    float* __restrict__ out)
{
    extern __shared__ float sm[];
    float4* sm4 = (float4*)sm;
    __shared__ float s_w[4];
    __shared__ int s_last;

    const int tid = threadIdx.x;
    const int b0 = blockIdx.x * BPB;

    // ---------------- staging (coalesced f4 gmem loads) ----------------
    {   // kw: 16*24 = 384 f4
        const float4* g = (const float4*)(kw + (size_t)b0 * 96);
#pragma unroll
        for (int r = 0; r < 3; ++r) {
            int i = tid + r * 128, b = i / 24, k = i - b * 24;
            sm4[KW4 + b * 25 + k] = __ldcs(&g[i]);
        }
    }
    {   // ik: 16*4*16 = 1024 f4 -> transposed [slot s][dest-thread]
        const float4* g = (const float4*)(ik + (size_t)b0 * 256);
#pragma unroll
        for (int r = 0; r < 8; ++r) {
            int i = tid + r * 128;
            int task = i >> 4, rem = i & 15;
            int h = rem >> 3, s = rem & 7;
            sm4[IK4 + s * 129 + 2 * task + h] = __ldcs(&g[i]);
        }
    }
    {   // cam: 16*12 = 192 f4 -> scalar scatter, odd stride
        const float4* g = (const float4*)(cam + (size_t)b0 * 48);
#pragma unroll
        for (int r = 0; r < 2; ++r) {
            int i = tid + r * 128;
            if (i < 192) {
                int b = i / 12, k = i - b * 12;
                float4 val = __ldcs(&g[i]);
                int base = CAMF + b * 49 + k * 4;
                sm[base] = val.x; sm[base + 1] = val.y;
                sm[base + 2] = val.z; sm[base + 3] = val.w;
            }
        }
    }
    {   // K: 16*9 = 144 f4
        const float4* g = (const float4*)(Kmat + (size_t)b0 * 36);
#pragma unroll
        for (int r = 0; r < 2; ++r) {
            int i = tid + r * 128;
            if (i < 144) {
                int b = i / 9, k = i - b * 9;
                float4 val = __ldcs(&g[i]);
                int base = KKF + b * 37 + k * 4;
                sm[base] = val.x; sm[base + 1] = val.y;
                sm[base + 2] = val.z; sm[base + 3] = val.w;
            }
        }
    }
    __syncthreads();

    // ------------- mapping: 2 threads per task, 16 joints each -------------
    const int h  = tid & 1;           // half (joints 16h .. 16h+15)
    const int v  = (tid >> 1) & 3;    // view
    const int bl = tid >> 3;          // local batch

    const float* cv = &sm[CAMF + bl * 49 + v * 12];
    const float R00=cv[0], R01=cv[1], R02=cv[2],  t0=cv[3];
    const float R10=cv[4], R11=cv[5], R12=cv[6],  t1=cv[7];
    const float R20=cv[8], R21=cv[9], R22=cv[10], t2=cv[11];
    const float* kp = &sm[KKF + bl * 37 + v * 9];
    const float K00=kp[0], K01=kp[1], c0=kp[2];
    const float K10=kp[3], K11=kp[4], c1=kp[5];

    const int xb = KW4 + bl * 25 + 12 * h;   // this half's 12 f4 of X

    // pass A: partial component sums over 16 joints -> pair-combined zbar
    float Sx = 0.f, Sy = 0.f, Sz = 0.f;
#pragma unroll
    for (int g = 0; g < 4; ++g) {
        float4 p0 = sm4[xb + g * 3];
        float4 p1 = sm4[xb + g * 3 + 1];
        float4 p2 = sm4[xb + g * 3 + 2];
        Sx += p0.x + p0.w + p1.z + p2.y;
        Sy += p0.y + p1.x + p1.w + p2.z;
        Sz += p0.z + p1.y + p2.x + p2.w;
    }
    float dpart = fmaf(R20, Sx, fmaf(R21, Sy, R22 * Sz));
    dpart += __shfl_xor_sync(0xFFFFFFFFu, dpart, 1);
    const float zbar = dpart * (1.0f / 32.0f) + t2;
    const float izb  = __fdividef(1.0f, zbar);

    // fold K * R * inv_z: uv = a . X + b
    const float a0x = izb * fmaf(K00, R00, K01 * R10);
    const float a0y = izb * fmaf(K00, R01, K01 * R11);
    const float a0z = izb * fmaf(K00, R02, K01 * R12);
    const float b0u = fmaf(izb, fmaf(K00, t0, K01 * t1), c0);
    const float a1x = izb * fmaf(K10, R00, K11 * R10);
    const float a1y = izb * fmaf(K10, R01, K11 * R11);
    const float a1z = izb * fmaf(K10, R02, K11 * R12);
    const float b1u = fmaf(izb, fmaf(K10, t0, K11 * t1), c1);

    // pass B: uv for 16 joints into regs + partial squared norms
    float2 uv[16];
    float np2 = 0.f, ni2 = 0.f;
#pragma unroll
    for (int g = 0; g < 4; ++g) {
        float4 p0 = sm4[xb + g * 3];
        float4 p1 = sm4[xb + g * 3 + 1];
        float4 p2 = sm4[xb + g * 3 + 2];
        float xs[4] = {p0.x, p0.w, p1.z, p2.y};
        float ys[4] = {p0.y, p1.x, p1.w, p2.z};
        float zs[4] = {p0.z, p1.y, p2.x, p2.w};
#pragma unroll
        for (int q = 0; q < 4; ++q) {
            int j = g * 4 + q;
            float ux = fmaf(a0x, xs[q], fmaf(a0y, ys[q], fmaf(a0z, zs[q], b0u)));
            float uy = fmaf(a1x, xs[q], fmaf(a1y, ys[q], fmaf(a1z, zs[q], b1u)));
            uv[j] = make_float2(ux, uy);
            np2 = fmaf(ux, ux, fmaf(uy, uy, np2));
        }
        float4 q0 = sm4[IK4 + (2 * g)     * 129 + tid];
        float4 q1 = sm4[IK4 + (2 * g + 1) * 129 + tid];
        ni2 = fmaf(q0.x, q0.x, fmaf(q0.y, q0.y, ni2));
        ni2 = fmaf(q0.z, q0.z, fmaf(q0.w, q0.w, ni2));
        ni2 = fmaf(q1.x, q1.x, fmaf(q1.y, q1.y, ni2));
        ni2 = fmaf(q1.z, q1.z, fmaf(q1.w, q1.w, ni2));
    }
    np2 += __shfl_xor_sync(0xFFFFFFFFu, np2, 1);
    ni2 += __shfl_xor_sync(0xFFFFFFFFu, ni2, 1);
    const float rp = rsqrtf(np2);
    const float ri = rsqrtf(ni2);

    // pass C: L1 of scale-free difference (uv from regs, ik re-read)
    float acc = 0.f;
#pragma unroll
    for (int g = 0; g < 4; ++g) {
        float4 q0 = sm4[IK4 + (2 * g)     * 129 + tid];
        float4 q1 = sm4[IK4 + (2 * g + 1) * 129 + tid];
        float qx[4] = {q0.x, q0.z, q1.x, q1.z};
        float qy[4] = {q0.y, q0.w, q1.y, q1.w};
#pragma unroll
        for (int q = 0; q < 4; ++q) {
            int j = g * 4 + q;
            acc += fabsf(fmaf(uv[j].x, rp, -qx[q] * ri))
                 + fabsf(fmaf(uv[j].y, rp, -qy[q] * ri));
        }
    }

    // ---------------- block partial + last-block deterministic reduce --------
    acc = warp_sum(acc);
    if ((tid & 31) == 0) s_w[tid >> 5] = acc;
    __syncthreads();
    if (tid == 0) {
        float bsum = s_w[0] + s_w[1] + s_w[2] + s_w[3];
        __stcg(&g_partials[blockIdx.x], bsum);
        __threadfence();
        unsigned int t = atomicAdd(&g_ticket, 1u);
        s_last = (t == NBLK - 1u);
    }
    __syncthreads();

    if (s_last) {
        float a = 0.f;
#pragma unroll
        for (int i = 0; i < NBLK / THREADS; ++i)
            a += __ldcg(&g_partials[tid * (NBLK / THREADS) + i]);
        a = warp_sum(a);
        if ((tid & 31) == 0) s_w[tid >> 5] = a;
        __syncthreads();
        if (tid == 0) {
            float tot = s_w[0] + s_w[1] + s_w[2] + s_w[3];
            out[0] = tot * (1.0f / (64.0f * (float)BB * (float)VV));
            g_ticket = 0u;
        }
    }
}

extern "C" void kernel_launch(void* const* d_in, const int* in_sizes, int n_in,
                              void* d_out, int out_size)
{
    const float* Kmat = (const float*)d_in[0];  // (B,V,3,3)
    const float* cam  = (const float*)d_in[1];  // (B,V,3,4)
    const float* kw   = (const float*)d_in[2];  // (B,J,3)
    const float* ik   = (const float*)d_in[3];  // (B,V,J,2)
    float* out = (float*)d_out;

    cudaFuncSetAttribute(proj_loss, cudaFuncAttributeMaxDynamicSharedMemorySize, SMEM_BYTES);
    proj_loss<<<NBLK, THREADS, SMEM_BYTES>>>(Kmat, cam, kw, ik, out);
}